// round 10
// baseline (speedup 1.0000x reference)
#include <cuda_runtime.h>

// ---------------------------------------------------------------------------
// Compile-time Clebsch-Gordan coefficients (Racah formula, double precision),
// baked into the fully-unrolled kernel as FFMA immediates.
// ---------------------------------------------------------------------------
namespace cg {

__host__ __device__ constexpr double cfact(int n) {
    double r = 1.0;
    for (int i = 2; i <= n; ++i) r *= (double)i;
    return r;
}

__host__ __device__ constexpr double csqrt(double x) {
    if (x <= 0.0) return 0.0;
    double r = x < 1.0 ? 1.0 : x;
    for (int i = 0; i < 100; ++i) r = 0.5 * (r + x / r);
    return r;
}

__host__ __device__ constexpr double clebsch(int j1, int m1, int j2, int m2, int j, int m) {
    if (m1 + m2 != m) return 0.0;
    double pre = csqrt((2.0 * j + 1.0) * cfact(j + j1 - j2) * cfact(j - j1 + j2) *
                       cfact(j1 + j2 - j) / cfact(j1 + j2 + j + 1));
    pre *= csqrt(cfact(j + m) * cfact(j - m) * cfact(j1 - m1) * cfact(j1 + m1) *
                 cfact(j2 - m2) * cfact(j2 + m2));
    double s = 0.0;
    int vmin = 0;
    if (j2 - j - m1 > vmin) vmin = j2 - j - m1;
    if (j1 + m2 - j > vmin) vmin = j1 + m2 - j;
    int vmax = j1 + j2 - j;
    if (j1 - m1 < vmax) vmax = j1 - m1;
    if (j2 + m2 < vmax) vmax = j2 + m2;
    for (int v = vmin; v <= vmax; ++v) {
        double d = cfact(v) * cfact(j1 + j2 - j - v) * cfact(j1 - m1 - v) *
                   cfact(j2 + m2 - v) * cfact(j - j2 + m1 + v) * cfact(j - j1 - m2 + v);
        s += ((v & 1) ? -1.0 : 1.0) / d;
    }
    return pre * s;
}

}  // namespace cg

// ---------------------------------------------------------------------------
// compile-time for
// ---------------------------------------------------------------------------
template <int V> struct Ic { static constexpr int value = V; };

template <int I, int N, class F>
__device__ __forceinline__ void cfor_(F&& f) {
    if constexpr (I < N) {
        f(Ic<I>{});
        cfor_<I + 1, N>(f);
    }
}
template <int N, class F>
__device__ __forceinline__ void cfor(F&& f) { cfor_<0, N>(f); }

// ---------------------------------------------------------------------------
// complex math on a pair of channels: float4 = {re0, im0, re1, im1}
// ---------------------------------------------------------------------------
__device__ __forceinline__ void cfma(float4& o, float c, const float4 u, const float4 v) {
    o.x += c * (u.x * v.x - u.y * v.y);
    o.y += c * (u.x * v.y + u.y * v.x);
    o.z += c * (u.z * v.z - u.w * v.w);
    o.w += c * (u.z * v.w + u.w * v.z);
}

template <int l1, int l2, int l>
__device__ __forceinline__ void contract(const float4* A, const float4* Bv, float4* out) {
    cfor<2 * l + 1>([&](auto M) { out[decltype(M)::value] = make_float4(0.f, 0.f, 0.f, 0.f); });
    cfor<(2 * l1 + 1) * (2 * l2 + 1)>([&](auto PQ) {
        constexpr int pq = decltype(PQ)::value;
        constexpr int p = pq / (2 * l2 + 1);
        constexpr int q = pq % (2 * l2 + 1);
        constexpr int m = (p - l1) + (q - l2);
        if constexpr (m >= -l && m <= l) {
            constexpr float c = (float)cg::clebsch(l1, p - l1, l2, q - l2, l, m);
            if constexpr (c != 0.0f) cfma(out[m + l], c, A[p], Bv[q]);
        }
    });
}

template <int l1, int l>
__device__ __forceinline__ void contract_sym(const float4* A, float4* out) {
    cfor<2 * l + 1>([&](auto M) { out[decltype(M)::value] = make_float4(0.f, 0.f, 0.f, 0.f); });
    cfor<(2 * l1 + 1) * (2 * l1 + 1)>([&](auto PQ) {
        constexpr int pq = decltype(PQ)::value;
        constexpr int p = pq / (2 * l1 + 1);
        constexpr int q = pq % (2 * l1 + 1);
        if constexpr (q >= p) {
            constexpr int m = (p - l1) + (q - l1);
            if constexpr (m >= -l && m <= l) {
                constexpr double c0 = cg::clebsch(l1, p - l1, l1, q - l1, l, m);
                constexpr float c = (float)((p == q) ? c0 : 2.0 * c0);
                if constexpr (c != 0.0f) cfma(out[m + l], c, A[p], A[q]);
            }
        }
    });
}

// ---------------------------------------------------------------------------
// Bulk async store helpers (SMEM -> GMEM through the TMA/async engine).
// ---------------------------------------------------------------------------
__device__ __forceinline__ void bulk_store(float4* gdst, const float4* ssrc, unsigned bytes) {
    unsigned saddr = (unsigned)__cvta_generic_to_shared((const void*)ssrc);
    asm volatile("cp.async.bulk.global.shared::cta.bulk_group [%0], [%1], %2;"
                 :: "l"((void*)gdst), "r"(saddr), "r"(bytes) : "memory");
}
__device__ __forceinline__ void bulk_commit() {
    asm volatile("cp.async.bulk.commit_group;" ::: "memory");
}
__device__ __forceinline__ void bulk_wait0() {
    asm volatile("cp.async.bulk.wait_group 0;" ::: "memory");
}
__device__ __forceinline__ void fence_async() {
    asm volatile("fence.proxy.async.shared::cta;" ::: "memory");
}

// ---------------------------------------------------------------------------
// Kernel. B=1024, T=512. Grid (4, 1024): blockIdx.x = piece, blockIdx.y = b.
// 256 threads; each thread owns 2 channels (one float4 per output row).
// Each piece computes its rows into an SMEM staging buffer (rows in gmem
// order) and emits 1-2 HUGE contiguous bulk async stores (36-86 KB each):
// within a part, all (m,slot) rows of one batch are contiguous in gmem.
//
//   piece 0: l0 part (3 rows) + l1 part (18 rows)   -> 12KB + 72KB bulk ops
//   piece 1: l2 part m=0..2 (18 rows)               -> 72KB bulk op
//   piece 2: l2 part m=3..4 (12 rows) + l4 (9 rows) -> 48KB + 36KB bulk ops
//   piece 3: l3 part (21 rows)                      -> 84KB bulk op
//
// Row = 256 float4 = 4KB. Dynamic SMEM = 21 rows = 86016 B -> 2 CTAs/SM.
// ---------------------------------------------------------------------------
__global__ void __launch_bounds__(256, 2) cg_kernel(
    const float4* __restrict__ X0, const float4* __restrict__ X1,
    const float4* __restrict__ X2, float4* __restrict__ O) {
    extern __shared__ float4 stage[];  // [row*256 + t]
    const unsigned piece = blockIdx.x;  // 0..3
    const unsigned b = blockIdx.y;
    const unsigned t = threadIdx.x;     // channel-pair 0..255

    float4 a0[1], a1[3], a2[5];
    cfor<3>([&](auto P) { constexpr int p = decltype(P)::value; a1[p] = X1[(b * 3u + p) * 256u + t]; });
    cfor<5>([&](auto P) { constexpr int p = decltype(P)::value; a2[p] = X2[(b * 5u + p) * 256u + t]; });

    const float4 Z = make_float4(0.f, 0.f, 0.f, 0.f);
    float4 o1[9], o2[9], o3[5], o4[5];

    if (piece == 0) {
        // rows 0..2: l0 slots; rows 3..20: l1 (m major, 6 slots each)
        a0[0] = X0[b * 256u + t];
        contract<0, 0, 0>(a0, a0, o1);
        stage[0u * 256u + t] = o1[0];
        contract_sym<1, 0>(a1, o1);
        stage[1u * 256u + t] = o1[0];
        contract_sym<2, 0>(a2, o1);
        stage[2u * 256u + t] = o1[0];

        contract<0, 1, 1>(a0, a1, o1);
        contract<1, 2, 1>(a1, a2, o2);
        cfor<3>([&](auto M) {
            constexpr int m = decltype(M)::value;
            const unsigned r = 3u + m * 6u;
            stage[(r + 0u) * 256u + t] = o1[m];  // (0,1,1)
            stage[(r + 1u) * 256u + t] = o1[m];  // (1,0,1)
            stage[(r + 2u) * 256u + t] = Z;      // (1,1,1) -> 0
            stage[(r + 3u) * 256u + t] = o2[m];  // (1,2,1)
            stage[(r + 4u) * 256u + t] = o2[m];  // (2,1,1)
            stage[(r + 5u) * 256u + t] = Z;      // (2,2,1) -> 0
        });
        __syncthreads();
        if (t == 0) {
            fence_async();
            bulk_store(&O[b * 768u], stage, 3u * 4096u);
            bulk_store(&O[786432u + b * 4608u], stage + 3u * 256u, 18u * 4096u);
            bulk_commit();
            bulk_wait0();
        }
    } else if (piece == 1 || piece == 2) {
        // l2 contractions (shared by pieces 1 & 2)
        a0[0] = X0[b * 256u + t];
        contract<0, 2, 2>(a0, a2, o1);   // (0,2,2) == (2,0,2)
        contract_sym<1, 2>(a1, o2);      // (1,1,2)
        contract<1, 2, 2>(a1, a2, o3);   // (1,2,2); (2,1,2) = -(1,2,2)
        contract_sym<2, 2>(a2, o4);      // (2,2,2)
        if (piece == 1) {
            // rows: m=0..2 x slots 0..5
            cfor<3>([&](auto M) {
                constexpr int m = decltype(M)::value;
                const unsigned r = m * 6u;
                stage[(r + 0u) * 256u + t] = o1[m];
                stage[(r + 1u) * 256u + t] = o2[m];
                stage[(r + 2u) * 256u + t] = o3[m];
                stage[(r + 3u) * 256u + t] = o1[m];
                stage[(r + 4u) * 256u + t] =
                    make_float4(-o3[m].x, -o3[m].y, -o3[m].z, -o3[m].w);
                stage[(r + 5u) * 256u + t] = o4[m];
            });
            __syncthreads();
            if (t == 0) {
                fence_async();
                bulk_store(&O[5505024u + b * 7680u], stage, 18u * 4096u);
                bulk_commit();
                bulk_wait0();
            }
        } else {
            // rows 0..11: l2 m=3..4; rows 12..20: l4 m=0..8
            cfor<2>([&](auto MM) {
                constexpr int m = decltype(MM)::value + 3;
                const unsigned r = (m - 3) * 6u;
                stage[(r + 0u) * 256u + t] = o1[m];
                stage[(r + 1u) * 256u + t] = o2[m];
                stage[(r + 2u) * 256u + t] = o3[m];
                stage[(r + 3u) * 256u + t] = o1[m];
                stage[(r + 4u) * 256u + t] =
                    make_float4(-o3[m].x, -o3[m].y, -o3[m].z, -o3[m].w);
                stage[(r + 5u) * 256u + t] = o4[m];
            });
            contract_sym<2, 4>(a2, o1);
            cfor<9>([&](auto M) {
                constexpr int m = decltype(M)::value;
                stage[(12u + m) * 256u + t] = o1[m];
            });
            __syncthreads();
            if (t == 0) {
                fence_async();
                bulk_store(&O[5505024u + b * 7680u + 4608u], stage, 12u * 4096u);
                bulk_store(&O[18874368u + b * 2304u], stage + 12u * 256u, 9u * 4096u);
                bulk_commit();
                bulk_wait0();
            }
        }
    } else {
        // l3 part: rows m*3 + {0,1,2}, 21 rows
        contract<1, 2, 3>(a1, a2, o1);
        cfor<7>([&](auto M) {
            constexpr int m = decltype(M)::value;
            const unsigned r = m * 3u;
            stage[(r + 0u) * 256u + t] = o1[m];  // (1,2,3)
            stage[(r + 1u) * 256u + t] = o1[m];  // (2,1,3)
            stage[(r + 2u) * 256u + t] = Z;      // (2,2,3) -> 0
        });
        __syncthreads();
        if (t == 0) {
            fence_async();
            bulk_store(&O[13369344u + b * 5376u], stage, 21u * 4096u);
            bulk_commit();
            bulk_wait0();
        }
    }
}

// ---------------------------------------------------------------------------
extern "C" void kernel_launch(void* const* d_in, const int* in_sizes, int n_in,
                              void* d_out, int out_size) {
    // Identify inputs by element count (robust to metadata ordering).
    const float* x0 = (const float*)d_in[0];
    const float* x1 = n_in > 1 ? (const float*)d_in[1] : nullptr;
    const float* x2 = n_in > 2 ? (const float*)d_in[2] : nullptr;
    for (int i = 0; i < n_in; ++i) {
        if (in_sizes[i] == 1024 * 1 * 512 * 2) x0 = (const float*)d_in[i];
        else if (in_sizes[i] == 1024 * 3 * 512 * 2) x1 = (const float*)d_in[i];
        else if (in_sizes[i] == 1024 * 5 * 512 * 2) x2 = (const float*)d_in[i];
    }
    const int smem_bytes = 21 * 4096;  // 86016
    static int attr_done = 0;
    if (!attr_done) {
        cudaFuncSetAttribute(cg_kernel, cudaFuncAttributeMaxDynamicSharedMemorySize,
                             smem_bytes);
        attr_done = 1;
    }
    dim3 grid(4, 1024);
    cg_kernel<<<grid, 256, smem_bytes>>>((const float4*)x0, (const float4*)x1,
                                         (const float4*)x2, (float4*)d_out);
}

// round 12
// speedup vs baseline: 1.0794x; 1.0794x over previous
#include <cuda_runtime.h>

// ---------------------------------------------------------------------------
// Compile-time Clebsch-Gordan coefficients (Racah formula, double precision),
// baked into the fully-unrolled kernel as FFMA immediates.
// ---------------------------------------------------------------------------
namespace cg {

__host__ __device__ constexpr double cfact(int n) {
    double r = 1.0;
    for (int i = 2; i <= n; ++i) r *= (double)i;
    return r;
}

__host__ __device__ constexpr double csqrt(double x) {
    if (x <= 0.0) return 0.0;
    double r = x < 1.0 ? 1.0 : x;
    for (int i = 0; i < 100; ++i) r = 0.5 * (r + x / r);
    return r;
}

__host__ __device__ constexpr double clebsch(int j1, int m1, int j2, int m2, int j, int m) {
    if (m1 + m2 != m) return 0.0;
    double pre = csqrt((2.0 * j + 1.0) * cfact(j + j1 - j2) * cfact(j - j1 + j2) *
                       cfact(j1 + j2 - j) / cfact(j1 + j2 + j + 1));
    pre *= csqrt(cfact(j + m) * cfact(j - m) * cfact(j1 - m1) * cfact(j1 + m1) *
                 cfact(j2 - m2) * cfact(j2 + m2));
    double s = 0.0;
    int vmin = 0;
    if (j2 - j - m1 > vmin) vmin = j2 - j - m1;
    if (j1 + m2 - j > vmin) vmin = j1 + m2 - j;
    int vmax = j1 + j2 - j;
    if (j1 - m1 < vmax) vmax = j1 - m1;
    if (j2 + m2 < vmax) vmax = j2 + m2;
    for (int v = vmin; v <= vmax; ++v) {
        double d = cfact(v) * cfact(j1 + j2 - j - v) * cfact(j1 - m1 - v) *
                   cfact(j2 + m2 - v) * cfact(j - j2 + m1 + v) * cfact(j - j1 - m2 + v);
        s += ((v & 1) ? -1.0 : 1.0) / d;
    }
    return pre * s;
}

}  // namespace cg

// ---------------------------------------------------------------------------
// compile-time for
// ---------------------------------------------------------------------------
template <int V> struct Ic { static constexpr int value = V; };

template <int I, int N, class F>
__device__ __forceinline__ void cfor_(F&& f) {
    if constexpr (I < N) {
        f(Ic<I>{});
        cfor_<I + 1, N>(f);
    }
}
template <int N, class F>
__device__ __forceinline__ void cfor(F&& f) { cfor_<0, N>(f); }

// ---------------------------------------------------------------------------
// complex math on a pair of channels: float4 = {re0, im0, re1, im1}
// ---------------------------------------------------------------------------
__device__ __forceinline__ void cfma(float4& o, float c, const float4 u, const float4 v) {
    o.x += c * (u.x * v.x - u.y * v.y);
    o.y += c * (u.x * v.y + u.y * v.x);
    o.z += c * (u.z * v.z - u.w * v.w);
    o.w += c * (u.z * v.w + u.w * v.z);
}

// General bilinear contraction out[m] = sum_{p,q} C[p,q,m] * A[p] (x) B[q]
template <int l1, int l2, int l>
__device__ __forceinline__ void contract(const float4* A, const float4* Bv, float4* out) {
    cfor<2 * l + 1>([&](auto M) { out[decltype(M)::value] = make_float4(0.f, 0.f, 0.f, 0.f); });
    cfor<(2 * l1 + 1) * (2 * l2 + 1)>([&](auto PQ) {
        constexpr int pq = decltype(PQ)::value;
        constexpr int p = pq / (2 * l2 + 1);
        constexpr int q = pq % (2 * l2 + 1);
        constexpr int m = (p - l1) + (q - l2);
        if constexpr (m >= -l && m <= l) {
            constexpr float c = (float)cg::clebsch(l1, p - l1, l2, q - l2, l, m);
            if constexpr (c != 0.0f) cfma(out[m + l], c, A[p], Bv[q]);
        }
    });
}

// Self-product with symmetric CG (even 2*l1 - l): fold p<q terms with 2*C.
template <int l1, int l>
__device__ __forceinline__ void contract_sym(const float4* A, float4* out) {
    cfor<2 * l + 1>([&](auto M) { out[decltype(M)::value] = make_float4(0.f, 0.f, 0.f, 0.f); });
    cfor<(2 * l1 + 1) * (2 * l1 + 1)>([&](auto PQ) {
        constexpr int pq = decltype(PQ)::value;
        constexpr int p = pq / (2 * l1 + 1);
        constexpr int q = pq % (2 * l1 + 1);
        if constexpr (q >= p) {
            constexpr int m = (p - l1) + (q - l1);
            if constexpr (m >= -l && m <= l) {
                constexpr double c0 = cg::clebsch(l1, p - l1, l1, q - l1, l, m);
                constexpr float c = (float)((p == q) ? c0 : 2.0 * c0);
                if constexpr (c != 0.0f) cfma(out[m + l], c, A[p], A[q]);
            }
        }
    });
}

// ---------------------------------------------------------------------------
// Kernel. B=1024, T=512. One block per batch b (256 threads), each thread
// handles 2 adjacent channels -> all global accesses are 16B (LDG/STG.128).
// Streaming (evict-first) stores: the 340MB output passes L2 exactly once.
// __launch_bounds__(256,2): regs capped at 128 so 2 CTAs/SM co-reside.
//
// Session conclusion: this kernel moves the compulsory-minimum bytes
// (340MB stores + 36MB loads) and is pinned at the HBM write-stream
// ceiling (~5.25TB/s, 64-65% of spec) -- verified invariant across store
// width (128/256-bit), cache policy, occupancy, CTA granularity, and TMA
// bulk async stores. Smallest grid wins on wall-clock launch overhead.
//
// Output layout (float4 units, parts l=0..4 concatenated, row-major
// (B, 2l+1, n_l*T, 2)):  idx = base_l + ((b*(2l+1)+m)*n_l + slot)*256 + t
// ---------------------------------------------------------------------------
__global__ void __launch_bounds__(256, 2) cg_kernel(
    const float4* __restrict__ X0, const float4* __restrict__ X1,
    const float4* __restrict__ X2, float4* __restrict__ O) {
    const unsigned b = blockIdx.x;
    const unsigned t = threadIdx.x;  // channel-pair 0..255

    float4 a0[1], a1[3], a2[5];
    a0[0] = X0[b * 256u + t];
    cfor<3>([&](auto P) { constexpr int p = decltype(P)::value; a1[p] = X1[(b * 3u + p) * 256u + t]; });
    cfor<5>([&](auto P) { constexpr int p = decltype(P)::value; a2[p] = X2[(b * 5u + p) * 256u + t]; });

    // part bases (float4 units)
    const unsigned P0 = 0u + b * 768u + t;          // l=0: n=3
    const unsigned P1 = 786432u + b * 4608u + t;    // l=1: n=6, m stride 1536
    const unsigned P2 = 5505024u + b * 7680u + t;   // l=2: n=6, m stride 1536
    const unsigned P3 = 13369344u + b * 5376u + t;  // l=3: n=3, m stride 768
    const unsigned P4 = 18874368u + b * 2304u + t;  // l=4: n=1, m stride 256
    const float4 Z = make_float4(0.f, 0.f, 0.f, 0.f);

    float4 out[9];

    // ---- l=0 part: slots {(0,0,0), (1,1,0), (2,2,0)} ----
    contract<0, 0, 0>(a0, a0, out);
    __stcs(&O[P0 + 0u], out[0]);
    contract_sym<1, 0>(a1, out);
    __stcs(&O[P0 + 256u], out[0]);
    contract_sym<2, 0>(a2, out);
    __stcs(&O[P0 + 512u], out[0]);

    // ---- l=1 part: slots {(0,1,1),(1,0,1),(1,1,1),(1,2,1),(2,1,1),(2,2,1)} ----
    contract<0, 1, 1>(a0, a1, out);
    cfor<3>([&](auto M) {
        constexpr int m = decltype(M)::value;
        __stcs(&O[P1 + m * 1536u + 0u],    out[m]);  // (0,1,1)
        __stcs(&O[P1 + m * 1536u + 256u],  out[m]);  // (1,0,1) == (0,1,1)
        __stcs(&O[P1 + m * 1536u + 512u],  Z);       // (1,1,1) antisymmetric -> 0
        __stcs(&O[P1 + m * 1536u + 1280u], Z);       // (2,2,1) antisymmetric -> 0
    });
    contract<1, 2, 1>(a1, a2, out);
    cfor<3>([&](auto M) {
        constexpr int m = decltype(M)::value;
        __stcs(&O[P1 + m * 1536u + 768u],  out[m]);  // (1,2,1)
        __stcs(&O[P1 + m * 1536u + 1024u], out[m]);  // (2,1,1) == (1,2,1)
    });

    // ---- l=2 part: slots {(0,2,2),(1,1,2),(1,2,2),(2,0,2),(2,1,2),(2,2,2)} ----
    contract<0, 2, 2>(a0, a2, out);
    cfor<5>([&](auto M) {
        constexpr int m = decltype(M)::value;
        __stcs(&O[P2 + m * 1536u + 0u],   out[m]);   // (0,2,2)
        __stcs(&O[P2 + m * 1536u + 768u], out[m]);   // (2,0,2) == (0,2,2)
    });
    contract_sym<1, 2>(a1, out);
    cfor<5>([&](auto M) {
        constexpr int m = decltype(M)::value;
        __stcs(&O[P2 + m * 1536u + 256u], out[m]);   // (1,1,2)
    });
    contract<1, 2, 2>(a1, a2, out);
    cfor<5>([&](auto M) {
        constexpr int m = decltype(M)::value;
        __stcs(&O[P2 + m * 1536u + 512u], out[m]);   // (1,2,2)
        __stcs(&O[P2 + m * 1536u + 1024u],           // (2,1,2) == -(1,2,2)
               make_float4(-out[m].x, -out[m].y, -out[m].z, -out[m].w));
    });
    contract_sym<2, 2>(a2, out);
    cfor<5>([&](auto M) {
        constexpr int m = decltype(M)::value;
        __stcs(&O[P2 + m * 1536u + 1280u], out[m]);  // (2,2,2)
    });

    // ---- l=3 part: slots {(1,2,3),(2,1,3),(2,2,3)} ----
    contract<1, 2, 3>(a1, a2, out);
    cfor<7>([&](auto M) {
        constexpr int m = decltype(M)::value;
        __stcs(&O[P3 + m * 768u + 0u],   out[m]);    // (1,2,3)
        __stcs(&O[P3 + m * 768u + 256u], out[m]);    // (2,1,3) == (1,2,3)
        __stcs(&O[P3 + m * 768u + 512u], Z);         // (2,2,3) antisymmetric -> 0
    });

    // ---- l=4 part: slot {(2,2,4)} ----
    contract_sym<2, 4>(a2, out);
    cfor<9>([&](auto M) {
        constexpr int m = decltype(M)::value;
        __stcs(&O[P4 + m * 256u], out[m]);
    });
}

// ---------------------------------------------------------------------------
extern "C" void kernel_launch(void* const* d_in, const int* in_sizes, int n_in,
                              void* d_out, int out_size) {
    // Identify inputs by element count (robust to metadata ordering).
    const float* x0 = (const float*)d_in[0];
    const float* x1 = n_in > 1 ? (const float*)d_in[1] : nullptr;
    const float* x2 = n_in > 2 ? (const float*)d_in[2] : nullptr;
    for (int i = 0; i < n_in; ++i) {
        if (in_sizes[i] == 1024 * 1 * 512 * 2) x0 = (const float*)d_in[i];
        else if (in_sizes[i] == 1024 * 3 * 512 * 2) x1 = (const float*)d_in[i];
        else if (in_sizes[i] == 1024 * 5 * 512 * 2) x2 = (const float*)d_in[i];
    }
    cg_kernel<<<1024, 256>>>((const float4*)x0, (const float4*)x1,
                             (const float4*)x2, (float4*)d_out);
}